// round 16
// baseline (speedup 1.0000x reference)
#include <cuda_runtime.h>
#include <cstdint>

// HONU order-2 as triangular register-blocked GEMM, split-K.
//   U[j][n] = W[p(j,n)] (n>=j) else 0;  Y = X U;  out = rowsum(Y .* X) + b
// R16: U operand moved OFF the smem crossbar (uniform LDS broadcast pays
// full 512 arch-bytes = 4 wf) onto the L1tex path: warp-uniform LDG.128 of
// pre-expanded A_g = 1 line = 1 wavefront, with an explicit depth-2
// prefetch rotation so L1 latency pipelines (fixes R11's serial-LDG bug).
// Shape = R14: warp (C,H), block A cols {4C..4C+3} half-trip 2C+2, block B
// cols {60-4C..63-4C} half-trip 32-2C -> 34 balanced iters/warp.
// 512 CTAs x 512 threads = 8192 warps.

#define THREADS 512
#define XT 33                    // xs_T row stride (floats)

__device__ __align__(16) float A_g[64 * 64];

__global__ void expand_kernel(const float* __restrict__ W) {
    int i = blockIdx.x * 256 + threadIdx.x;            // 4096 elements
    if (i < 64 * 64) {
        int j = i >> 6, n = i & 63;
        float v = 0.0f;
        if (n >= j) v = W[j * 64 - ((j * (j - 1)) >> 1) + (n - j)];
        A_g[i] = v;
    }
}

__device__ __forceinline__ void fma2(uint64_t& d, uint64_t a, uint64_t b) {
    asm("fma.rn.f32x2 %0, %1, %2, %0;" : "+l"(d) : "l"(a), "l"(b));
}
__device__ __forceinline__ float lds32(unsigned addr) {
    float v;
    asm volatile("ld.shared.f32 %0, [%1];" : "=f"(v) : "r"(addr));
    return v;
}
__device__ __forceinline__ uint64_t splat(float x) {
    uint64_t d;
    asm("mov.b64 %0, {%1,%1};" : "=l"(d) : "r"(__float_as_uint(x)));
    return d;
}
__device__ __forceinline__ uint64_t pack2(uint32_t lo, uint32_t hi) {
    uint64_t d;
    asm("mov.b64 %0, {%1,%2};" : "=l"(d) : "r"(lo), "r"(hi));
    return d;
}
__device__ __forceinline__ float lo32(uint64_t v) {
    uint32_t r; asm("mov.b64 {%0,_}, %1;" : "=r"(r) : "l"(v));
    return __uint_as_float(r);
}
__device__ __forceinline__ float hi32(uint64_t v) {
    uint32_t r; asm("mov.b64 {_,%0}, %1;" : "=r"(r) : "l"(v));
    return __uint_as_float(r);
}

// One column block: trip N iterations from k0, cols at uint4 index cidx.
// Depth-2 LDG prefetch rotation; x from smem (1 wf per load).
template <int N>
__device__ __forceinline__ void block(unsigned xtb, const uint4* __restrict__ Ag,
                                      int k0, int cidx,
                                      uint64_t& acc0, uint64_t& acc1) {
    uint4 buf0, buf1;
    buf0 = __ldg(Ag + (size_t)(k0 + 0) * 16 + cidx);
    if (N > 1) buf1 = __ldg(Ag + (size_t)(k0 + 1) * 16 + cidx);
    #pragma unroll
    for (int i = 0; i < N; ++i) {
        uint4 uc = (i & 1) ? buf1 : buf0;
        if (i + 2 < N) {                     // prefetch k0+i+2
            uint4 nv = __ldg(Ag + (size_t)(k0 + i + 2) * 16 + cidx);
            if (i & 1) buf1 = nv; else buf0 = nv;
        }
        uint64_t xk2 = splat(lds32(xtb + (k0 + i) * (XT * 4)));
        fma2(acc0, pack2(uc.x, uc.y), xk2);
        fma2(acc1, pack2(uc.z, uc.w), xk2);
    }
}

template <int C, int H>
__device__ __forceinline__ float body(unsigned xtb, const uint4* __restrict__ Ag) {
    constexpr int colA = 4 * C;
    constexpr int colB = 60 - 4 * C;
    constexpr int hA   = 2 * C + 2;       // half-trip, block A
    constexpr int hB   = 32 - 2 * C;      // half-trip, block B

    uint64_t a0 = 0, a1 = 0, b0 = 0, b1 = 0;
    block<hA>(xtb, Ag, H * hA, C,      a0, a1);
    block<hB>(xtb, Ag, H * hB, 15 - C, b0, b1);

    float p = 0.0f;
    p = fmaf(lo32(a0), lds32(xtb + (colA + 0) * (XT * 4)), p);
    p = fmaf(hi32(a0), lds32(xtb + (colA + 1) * (XT * 4)), p);
    p = fmaf(lo32(a1), lds32(xtb + (colA + 2) * (XT * 4)), p);
    p = fmaf(hi32(a1), lds32(xtb + (colA + 3) * (XT * 4)), p);
    p = fmaf(lo32(b0), lds32(xtb + (colB + 0) * (XT * 4)), p);
    p = fmaf(hi32(b0), lds32(xtb + (colB + 1) * (XT * 4)), p);
    p = fmaf(lo32(b1), lds32(xtb + (colB + 2) * (XT * 4)), p);
    p = fmaf(hi32(b1), lds32(xtb + (colB + 3) * (XT * 4)), p);
    return p;
}

__global__ void __launch_bounds__(THREADS, 2) honu_kernel(
    const float* __restrict__ x, const float* __restrict__ bias,
    float* __restrict__ out)
{
    __shared__ float xs_T[64 * XT];                  // 8.25 KB transposed
    __shared__ float part[16][32];                   // 2 KB

    const int tid  = threadIdx.x;
    const int wid  = tid >> 5;
    const int lane = tid & 31;
    const int row0 = blockIdx.x * 32;

    // --- Stage x tile transposed: xs_T[k][r] = x[row0+r][k] (1 float4/thread)
    {
        const float4* xg4 = reinterpret_cast<const float4*>(x + (size_t)row0 * 64);
        int r = tid >> 4, c4 = tid & 15;             // 512 float4s
        float4 v = xg4[tid];
        xs_T[(4 * c4 + 0) * XT + r] = v.x;
        xs_T[(4 * c4 + 1) * XT + r] = v.y;
        xs_T[(4 * c4 + 2) * XT + r] = v.z;
        xs_T[(4 * c4 + 3) * XT + r] = v.w;
    }
    __syncthreads();

    const unsigned xtb = (unsigned)__cvta_generic_to_shared(xs_T) + lane * 4;
    const uint4* Ag = reinterpret_cast<const uint4*>(A_g);

    float p;
    switch (wid) {
        case 0:  p = body<0, 0>(xtb, Ag); break;
        case 1:  p = body<0, 1>(xtb, Ag); break;
        case 2:  p = body<1, 0>(xtb, Ag); break;
        case 3:  p = body<1, 1>(xtb, Ag); break;
        case 4:  p = body<2, 0>(xtb, Ag); break;
        case 5:  p = body<2, 1>(xtb, Ag); break;
        case 6:  p = body<3, 0>(xtb, Ag); break;
        case 7:  p = body<3, 1>(xtb, Ag); break;
        case 8:  p = body<4, 0>(xtb, Ag); break;
        case 9:  p = body<4, 1>(xtb, Ag); break;
        case 10: p = body<5, 0>(xtb, Ag); break;
        case 11: p = body<5, 1>(xtb, Ag); break;
        case 12: p = body<6, 0>(xtb, Ag); break;
        case 13: p = body<6, 1>(xtb, Ag); break;
        case 14: p = body<7, 0>(xtb, Ag); break;
        default: p = body<7, 1>(xtb, Ag); break;
    }

    part[wid][lane] = p;
    __syncthreads();

    // --- Warp 0 combines the 16 (C,H) partials per row
    if (wid == 0) {
        float s = part[0][lane];
        #pragma unroll
        for (int c = 1; c < 16; ++c) s += part[c][lane];
        out[row0 + lane] = s + __ldg(bias);
    }
}

extern "C" void kernel_launch(void* const* d_in, const int* in_sizes, int n_in,
                              void* d_out, int out_size) {
    const float* x = (const float*)d_in[0];   // (16384, 64) f32
    const float* W = (const float*)d_in[1];   // (2145,)  f32 (first 2080 used)
    const float* b = (const float*)d_in[2];   // (1,)     f32
    float*     out = (float*)d_out;           // (16384,) f32

    expand_kernel<<<16, 256>>>(W);

    const int blocks = out_size / 32;         // 512 CTAs x 512 threads
    honu_kernel<<<blocks, THREADS>>>(x, b, out);
}

// round 17
// speedup vs baseline: 1.2371x; 1.2371x over previous
#include <cuda_runtime.h>
#include <cstdint>

// HONU order-2 as triangular 2D-register-tiled GEMM.
//   U[j][n] = W[p(j,n)] (n>=j) else 0;  Y = X U;  out = rowsum(Y .* X) + b
// Thread tile: 4 rows (strided: rowg+16j) x 8 cols (paired blocks
// A={4g..4g+3}, B={60-4g..63-4g}) -> per iter 4 x-scalars + 1 U LDS.128
// feed 8 FMA2 (2 arch-B per lane-FMA, 2.5x less crossbar than R14).
// CTA 256 thr (rowg 0..15, cgbit, warp=(cH,H)), 64 rows; 256 CTAs = 2048
// warps. Trips: A to 8cH+8, B to 64-8cH (pair-ragged tail multiplies U's
// zero lower triangle). Per-H 36 balanced iters. Single kernel.

#define THREADS 256
#define XST 65                   // xs_T row stride in floats (260 B)

__device__ __forceinline__ void fma2(uint64_t& d, uint64_t a, uint64_t b) {
    asm("fma.rn.f32x2 %0, %1, %2, %0;" : "+l"(d) : "l"(a), "l"(b));
}
__device__ __forceinline__ void lds_v2u64(uint64_t& a, uint64_t& b, unsigned addr) {
    asm volatile("ld.shared.v2.b64 {%0,%1}, [%2];" : "=l"(a), "=l"(b) : "r"(addr));
}
__device__ __forceinline__ float lds32(unsigned addr) {
    float v;
    asm volatile("ld.shared.f32 %0, [%1];" : "=f"(v) : "r"(addr));
    return v;
}
__device__ __forceinline__ uint64_t splat(float x) {
    uint64_t d;
    asm("mov.b64 %0, {%1,%1};" : "=l"(d) : "r"(__float_as_uint(x)));
    return d;
}
__device__ __forceinline__ float lo32(uint64_t v) {
    uint32_t r; asm("mov.b64 {%0,_}, %1;" : "=r"(r) : "l"(v));
    return __uint_as_float(r);
}
__device__ __forceinline__ float hi32(uint64_t v) {
    uint32_t r; asm("mov.b64 {_,%0}, %1;" : "=r"(r) : "l"(v));
    return __uint_as_float(r);
}

// xb = xs_T base + rowg*4 ; ub = U_s base. Row j of this lane = rowg + 16j:
// x[k][row_j] at byte xb + k*260 + j*64.
template <int CH>
__device__ __forceinline__ void body(unsigned xb, unsigned ub, int H, int cgbit,
                                     float p[4]) {
    constexpr int TA = 4 * CH + 4;        // per-H trip, block A
    constexpr int TB = 32 - 4 * CH;       // per-H trip, block B
    const int colA0 = (2 * CH + cgbit) * 4;
    const int colB0 = 60 - colA0;

    uint64_t aP[8] = {0,0,0,0,0,0,0,0};   // [j*2+p] block A
    uint64_t bP[8] = {0,0,0,0,0,0,0,0};   // [j*2+p] block B

    {   // block A: k = H*TA .. H*TA+TA-1  (covers k <= colA0+3 incl. pad)
        const unsigned xA = xb + (H * TA) * (XST * 4);
        const unsigned uA = ub + (H * TA) * 256 + colA0 * 4;
        #pragma unroll
        for (int i = 0; i < TA; ++i) {
            uint64_t u0, u1;
            lds_v2u64(u0, u1, uA + i * 256);           // U[k][colA0..+3]
            #pragma unroll
            for (int j = 0; j < 4; ++j) {
                uint64_t xk = splat(lds32(xA + i * (XST * 4) + j * 64));
                fma2(aP[j * 2 + 0], u0, xk);
                fma2(aP[j * 2 + 1], u1, xk);
            }
        }
    }
    {   // block B: k = H*TB .. H*TB+TB-1
        const unsigned xB = xb + (H * TB) * (XST * 4);
        const unsigned uB = ub + (H * TB) * 256 + colB0 * 4;
        #pragma unroll
        for (int i = 0; i < TB; ++i) {
            uint64_t u0, u1;
            lds_v2u64(u0, u1, uB + i * 256);
            #pragma unroll
            for (int j = 0; j < 4; ++j) {
                uint64_t xk = splat(lds32(xB + i * (XST * 4) + j * 64));
                fma2(bP[j * 2 + 0], u0, xk);
                fma2(bP[j * 2 + 1], u1, xk);
            }
        }
    }

    // Partial dot: p[j] = sum over this thread's 8 cols of y * x[row_j][col]
    const unsigned xcA = xb + colA0 * (XST * 4);
    const unsigned xcB = xb + colB0 * (XST * 4);
    #pragma unroll
    for (int j = 0; j < 4; ++j) {
        float s;
        s  = lo32(aP[j*2+0]) * lds32(xcA + 0*(XST*4) + j*64);
        s += hi32(aP[j*2+0]) * lds32(xcA + 1*(XST*4) + j*64);
        s += lo32(aP[j*2+1]) * lds32(xcA + 2*(XST*4) + j*64);
        s += hi32(aP[j*2+1]) * lds32(xcA + 3*(XST*4) + j*64);
        s += lo32(bP[j*2+0]) * lds32(xcB + 0*(XST*4) + j*64);
        s += hi32(bP[j*2+0]) * lds32(xcB + 1*(XST*4) + j*64);
        s += lo32(bP[j*2+1]) * lds32(xcB + 2*(XST*4) + j*64);
        s += hi32(bP[j*2+1]) * lds32(xcB + 3*(XST*4) + j*64);
        p[j] = s;
    }
}

__global__ void __launch_bounds__(THREADS) honu_kernel(
    const float* __restrict__ x, const float* __restrict__ W,
    const float* __restrict__ bias, float* __restrict__ out)
{
    __shared__ __align__(16) float U_s[64 * 64];     // 16 KB zero-filled
    __shared__ float xs_T[64 * XST];                 // 16.25 KB k-major
    __shared__ float part[8][64];                    // 2 KB

    const int tid   = threadIdx.x;
    const int wid   = tid >> 5;
    const int lane  = tid & 31;
    const int rowg  = lane & 15;
    const int cgbit = lane >> 4;
    const int row0  = blockIdx.x * 64;

    // --- Expand U from packed W (16 elements/thread; W L2-resident)
    #pragma unroll
    for (int it = 0; it < 16; ++it) {
        int e = it * THREADS + tid;                  // 0..4095
        int j = e >> 6, n = e & 63;
        float v = 0.0f;
        if (n >= j) v = __ldg(&W[j * 64 - ((j * (j - 1)) >> 1) + (n - j)]);
        U_s[e] = v;
    }
    // --- Stage x tile k-major: xs_T[k][r] = x[row0+r][k], stride 65
    {
        const float4* xg4 = reinterpret_cast<const float4*>(x + (size_t)row0 * 64);
        #pragma unroll
        for (int it = 0; it < 4; ++it) {
            int i = it * THREADS + tid;              // 0..1023 float4s
            int r = i >> 4, c4 = i & 15;
            float4 v = xg4[i];
            xs_T[(4 * c4 + 0) * XST + r] = v.x;
            xs_T[(4 * c4 + 1) * XST + r] = v.y;
            xs_T[(4 * c4 + 2) * XST + r] = v.z;
            xs_T[(4 * c4 + 3) * XST + r] = v.w;
        }
    }
    __syncthreads();

    const unsigned xb = (unsigned)__cvta_generic_to_shared(xs_T) + rowg * 4;
    const unsigned ub = (unsigned)__cvta_generic_to_shared(U_s);
    const int H = wid & 1;

    float p[4];
    switch (wid >> 1) {
        case 0:  body<0>(xb, ub, H, cgbit, p); break;
        case 1:  body<1>(xb, ub, H, cgbit, p); break;
        case 2:  body<2>(xb, ub, H, cgbit, p); break;
        default: body<3>(xb, ub, H, cgbit, p); break;
    }

    // --- Combine the two cgbit lanes (same rows, different col sets)
    #pragma unroll
    for (int j = 0; j < 4; ++j)
        p[j] += __shfl_xor_sync(0xffffffffu, p[j], 16);

    if (cgbit == 0) {
        #pragma unroll
        for (int j = 0; j < 4; ++j)
            part[wid][rowg + 16 * j] = p[j];
    }
    __syncthreads();

    // --- First 64 threads: sum the 8 (cH,H) partials per row
    if (tid < 64) {
        float s = part[0][tid];
        #pragma unroll
        for (int c = 1; c < 8; ++c) s += part[c][tid];
        out[row0 + tid] = s + __ldg(bias);
    }
}

extern "C" void kernel_launch(void* const* d_in, const int* in_sizes, int n_in,
                              void* d_out, int out_size) {
    const float* x = (const float*)d_in[0];   // (16384, 64) f32
    const float* W = (const float*)d_in[1];   // (2145,)  f32 (first 2080 used)
    const float* b = (const float*)d_in[2];   // (1,)     f32
    float*     out = (float*)d_out;           // (16384,) f32

    const int blocks = out_size / 64;         // 256 CTAs x 256 threads
    honu_kernel<<<blocks, THREADS>>>(x, W, b, out);
}